// round 14
// baseline (speedup 1.0000x reference)
#include <cuda_runtime.h>
#include <cuda_fp16.h>
#include <cuda_fp8.h>
#include <math.h>
#include <stdint.h>

#define A_DIM 4608
#define L_DIM 4096
#define H_DIM 192
#define W_DIM 192
#define NTILE 36
#define NTILES_TOTAL (NTILE * NTILE)
#define NIT16 128
#define NIT   256
#define PITCH 80
#define STAGE (256 * PITCH)
#define NSTG  3
#define SMEM_BYTES (NSTG * STAGE)
#define NPERS 296

__device__ __half g_styHi[(size_t)A_DIM * L_DIM];
__device__ __half g_imgHi[(size_t)A_DIM * L_DIM];
__device__ unsigned char g_A8[(size_t)A_DIM * 2 * L_DIM];
__device__ unsigned char g_B8[(size_t)A_DIM * 2 * L_DIM];
__device__ float g_invImg[A_DIM];
__device__ float g_invSty[A_DIM];
__device__ float g_np[2 * A_DIM * 8];
__device__ float g_pmax[NTILE * A_DIM];
__device__ int   g_pidx[NTILE * A_DIM];
__device__ unsigned int g_tileCtr;

__device__ __forceinline__ uint32_t smem_u32(const void* p) {
    uint32_t a;
    asm("{ .reg .u64 t; cvta.to.shared.u64 t, %1; cvt.u32.u64 %0, t; }" : "=r"(a) : "l"(p));
    return a;
}
#define CP16(dst, src) \
    asm volatile("cp.async.cg.shared.global [%0], [%1], 16;" :: "r"(dst), "l"(src) : "memory")
#define CP_COMMIT() asm volatile("cp.async.commit_group;" ::: "memory")
#define CP_WAIT1()  asm volatile("cp.async.wait_group 1;" ::: "memory")
#define CP_WAIT0()  asm volatile("cp.async.wait_group 0;" ::: "memory")
#define LDSM4(r0, r1, r2, r3, a) \
    asm volatile("ldmatrix.sync.aligned.m8n8.x4.shared.b16 {%0,%1,%2,%3}, [%4];" \
        : "=r"(r0), "=r"(r1), "=r"(r2), "=r"(r3) : "r"(a))
#define MMA_F16(c, a, b) \
    asm volatile("mma.sync.aligned.m16n8k16.row.col.f32.f16.f16.f32 " \
        "{%0,%1,%2,%3}, {%4,%5,%6,%7}, {%8,%9}, {%0,%1,%2,%3};" \
        : "+f"((c)[0]), "+f"((c)[1]), "+f"((c)[2]), "+f"((c)[3]) \
        : "r"((a)[0]), "r"((a)[1]), "r"((a)[2]), "r"((a)[3]), "r"((b)[0]), "r"((b)[1]))
#define MMA_F8(c, a, b) \
    asm volatile("mma.sync.aligned.m16n8k32.row.col.f32.e4m3.e4m3.f32 " \
        "{%0,%1,%2,%3}, {%4,%5,%6,%7}, {%8,%9}, {%0,%1,%2,%3};" \
        : "+f"((c)[0]), "+f"((c)[1]), "+f"((c)[2]), "+f"((c)[3]) \
        : "r"((a)[0]), "r"((a)[1]), "r"((a)[2]), "r"((a)[3]), "r"((b)[0]), "r"((b)[1]))

__device__ __forceinline__ unsigned char to_e4m3(float f) {
    return (unsigned char)__nv_cvt_float_to_fp8(f, __NV_SATFINITE, __NV_E4M3);
}

// ---------------------------------------------------------------------------
// 1) unfold + fp16 hi + fp8 correction operands + norm partials.
//    which=0: model (GEMM B / columns). which=1: style (GEMM A / rows).
// ---------------------------------------------------------------------------
__global__ void __launch_bounds__(192)
unfold_part(const float* __restrict__ in, int which) {
    __shared__ float sh[576];
    __shared__ float red[9][64];
    const int c = blockIdx.x, phc = blockIdx.y;
    const int tid = threadIdx.x;
    const float* src = in + (size_t)c * H_DIM * W_DIM;

    float acc0 = 0.0f, acc1 = 0.0f, acc2 = 0.0f;
    for (int pp = 0; pp < 8; ++pp) {
        const int ph = phc * 8 + pp;
        const float* rsrc = src + ph * 3 * W_DIM;
        sh[tid]       = rsrc[tid];
        sh[tid + 192] = rsrc[tid + 192];
        sh[tid + 384] = rsrc[tid + 384];
        __syncthreads();
        #pragma unroll
        for (int j = 0; j < 3; ++j) {
            int i = tid + j * 192;
            int seg = i >> 6, pw = i & 63;
            int kh = seg / 3, kw = seg - kh * 3;
            float v = sh[kh * W_DIM + pw * 3 + kw];
            __half hi = __float2half_rn(v);
            float hif = __half2float(hi);
            float lo = v - hif;
            int a = c * 9 + seg;
            int l = ph * 64 + pw;
            size_t o  = (size_t)a * L_DIM + l;
            size_t o8 = (size_t)a * (2 * L_DIM) + l;
            if (which) {   // style -> GEMM A rows
                g_styHi[o] = hi;
                g_A8[o8]         = to_e4m3(hif * 0.0625f);   // hi * 2^-4
                g_A8[o8 + L_DIM] = to_e4m3(lo * 32.0f);      // lo * 2^5
            } else {       // model -> GEMM B cols
                g_imgHi[o] = hi;
                g_B8[o8]         = to_e4m3(lo * 16.0f);      // lo * 2^4
                g_B8[o8 + L_DIM] = to_e4m3(hif * 0.03125f);  // hi * 2^-5
            }
            if (j == 0) acc0 = fmaf(v, v, acc0);
            else if (j == 1) acc1 = fmaf(v, v, acc1);
            else acc2 = fmaf(v, v, acc2);
        }
        __syncthreads();
    }
    red[(tid >> 6)][tid & 63]     = acc0;
    red[3 + (tid >> 6)][tid & 63] = acc1;
    red[6 + (tid >> 6)][tid & 63] = acc2;
    __syncthreads();
    if (tid < 9) {
        float s = 0.0f;
        #pragma unroll 8
        for (int k = 0; k < 64; ++k) s += red[tid][k];
        g_np[((size_t)which * A_DIM + c * 9 + tid) * 8 + phc] = s;
    }
}

// ---------------------------------------------------------------------------
// 2) norm finish + tile-counter reset
// ---------------------------------------------------------------------------
__global__ void norm_finish() {
    int i = blockIdx.x * blockDim.x + threadIdx.x;
    if (i == 0) g_tileCtr = 0;
    if (i >= 2 * A_DIM) return;
    float s = 0.0f;
    #pragma unroll
    for (int k = 0; k < 8; ++k) s += g_np[(size_t)i * 8 + k];
    float inv = 1.0f / sqrtf(s);
    if (i < A_DIM) g_invImg[i] = inv;          // model norms (row scaling)
    else           g_invSty[i - A_DIM] = inv;  // style norms (output scaling)
}

// ---------------------------------------------------------------------------
// 3) persistent mixed fp16/fp8 GEMM, 128x128 tile, 4 warps (64x64 each).
//    iters 0..127: fp16 hi*hi (BK=32). iters 128..255: e4m3 correction (BK=64).
// ---------------------------------------------------------------------------
__global__ void __launch_bounds__(128, 2)
gemm_mma() {
    extern __shared__ char smem[];
    __shared__ int sh_tile;
    const uint32_t sb = smem_u32(smem);
    const int tid = threadIdx.x;
    const int wid = tid >> 5, lane = tid & 31;
    const int warp_m = wid & 1, warp_n = wid >> 1;
    const int m_base = warp_m * 64, n_base = warp_n * 64;

    const uint32_t aOff = (uint32_t)(m_base + (lane & 15)) * PITCH + (lane >> 4) * 16;
    const uint32_t bOff = 128u * PITCH
                        + (uint32_t)(n_base + ((lane >> 4) * 8) + (lane & 7)) * PITCH
                        + (((lane >> 3) & 1) * 16);

    for (;;) {
        if (tid == 0) sh_tile = (int)atomicAdd(&g_tileCtr, 1u);
        __syncthreads();
        const int tile = sh_tile;
        if (tile >= NTILES_TOTAL) break;
        const int bm = tile / NTILE, bn = tile - bm * NTILE;
        const int m0 = bm * 128, n0 = bn * 128;

        const char* a16 = (const char*)(g_styHi + (size_t)m0 * L_DIM);
        const char* b16 = (const char*)(g_imgHi + (size_t)n0 * L_DIM);
        const char* a8  = (const char*)g_A8 + (size_t)m0 * (2 * L_DIM);
        const char* b8  = (const char*)g_B8 + (size_t)n0 * (2 * L_DIM);

        auto issue = [&](int it, int s) {
            const uint32_t st = sb + s * STAGE;
            const char *bA, *bB;
            size_t off;
            if (it < NIT16) {
                off = (size_t)it * 64;
                bA = a16; bB = b16;
            } else {
                off = (size_t)(it - NIT16) * 64;
                bA = a8;  bB = b8;
            }
            const size_t str = 2 * (size_t)L_DIM;   // row stride bytes, both phases
            #pragma unroll
            for (int u = 0; u < 8; ++u) {
                int idx = u * 128 + tid;
                int row = idx >> 2, col = idx & 3;
                const char* g = (row < 128)
                    ? bA + (size_t)row * str + off + col * 16
                    : bB + (size_t)(row - 128) * str + off + col * 16;
                CP16(st + row * PITCH + col * 16, g);
            }
            CP_COMMIT();
        };

        float acc[4][8][4];
        #pragma unroll
        for (int i = 0; i < 4; ++i)
            #pragma unroll
            for (int j = 0; j < 8; ++j)
                #pragma unroll
                for (int k = 0; k < 4; ++k) acc[i][j][k] = 0.0f;

        issue(0, 0);
        issue(1, 1);

        for (int it = 0; it < NIT; ++it) {
            const int s = it % NSTG;
            if (it + 2 < NIT) { CP_WAIT1(); } else { CP_WAIT0(); }
            __syncthreads();
            if (it + 2 < NIT) issue(it + 2, (it + 2) % NSTG);

            const uint32_t st = sb + s * STAGE;
            #pragma unroll
            for (int ks = 0; ks < 2; ++ks) {
                uint32_t a0[4][4];
                #pragma unroll
                for (int mt = 0; mt < 4; ++mt)
                    LDSM4(a0[mt][0], a0[mt][1], a0[mt][2], a0[mt][3],
                          st + aOff + mt * 16 * PITCH + ks * 32);
                uint32_t b0[4][4];
                #pragma unroll
                for (int np = 0; np < 4; ++np)
                    LDSM4(b0[np][0], b0[np][1], b0[np][2], b0[np][3],
                          st + bOff + np * 16 * PITCH + ks * 32);
                if (it < NIT16) {
                    #pragma unroll
                    for (int mt = 0; mt < 4; ++mt)
                        #pragma unroll
                        for (int np = 0; np < 4; ++np) {
                            MMA_F16(acc[mt][np * 2],     a0[mt], (&b0[np][0]));
                            MMA_F16(acc[mt][np * 2 + 1], a0[mt], (&b0[np][2]));
                        }
                } else {
                    #pragma unroll
                    for (int mt = 0; mt < 4; ++mt)
                        #pragma unroll
                        for (int np = 0; np < 4; ++np) {
                            MMA_F8(acc[mt][np * 2],     a0[mt], (&b0[np][0]));
                            MMA_F8(acc[mt][np * 2 + 1], a0[mt], (&b0[np][2]));
                        }
                }
            }
            __syncthreads();
        }

        // ---- register epilogue: column max of acc * g_invImg[row] ----
        float invR[8];
        #pragma unroll
        for (int mt = 0; mt < 4; ++mt)
            #pragma unroll
            for (int h = 0; h < 2; ++h)
                invR[mt * 2 + h] = g_invImg[m0 + m_base + mt * 16 + h * 8 + (lane >> 2)];

        float* pv = (float*)smem;
        int*   pi = (int*)(smem + 2 * 128 * 4);

        #pragma unroll
        for (int j = 0; j < 8; ++j)
            #pragma unroll
            for (int p = 0; p < 2; ++p) {
                float bv = -3.402823466e38f;
                int bi = 0x7fffffff;
                #pragma unroll
                for (int mt = 0; mt < 4; ++mt)
                    #pragma unroll
                    for (int h = 0; h < 2; ++h) {
                        float v = acc[mt][j][h * 2 + p] * invR[mt * 2 + h];
                        int row = m0 + m_base + mt * 16 + h * 8 + (lane >> 2);
                        if (v > bv || (v == bv && row < bi)) { bv = v; bi = row; }
                    }
                #pragma unroll
                for (int o = 4; o < 32; o <<= 1) {
                    float ov = __shfl_xor_sync(0xffffffffu, bv, o);
                    int   oi = __shfl_xor_sync(0xffffffffu, bi, o);
                    if (ov > bv || (ov == bv && oi < bi)) { bv = ov; bi = oi; }
                }
                if ((lane >> 2) == 0) {
                    int col = n_base + j * 8 + (lane & 3) * 2 + p;
                    pv[warp_m * 128 + col] = bv;
                    pi[warp_m * 128 + col] = bi;
                }
            }
        __syncthreads();

        if (tid < 128) {
            float bv = pv[tid];
            int bi = pi[tid];
            float v = pv[128 + tid];
            int  i2 = pi[128 + tid];
            if (v > bv || (v == bv && i2 < bi)) { bv = v; bi = i2; }
            g_pmax[bm * A_DIM + n0 + tid] = bv;
            g_pidx[bm * A_DIM + n0 + tid] = bi;
        }
        __syncthreads();
    }
}

// ---------------------------------------------------------------------------
// 4) final reduce (scale by style norms)
// ---------------------------------------------------------------------------
__global__ void final_kernel(float* __restrict__ out) {
    int j = blockIdx.x * blockDim.x + threadIdx.x;
    if (j >= A_DIM) return;
    float bv = g_pmax[j];
    int bi = g_pidx[j];
    #pragma unroll
    for (int t = 1; t < NTILE; ++t) {
        float v = g_pmax[t * A_DIM + j];
        int i = g_pidx[t * A_DIM + j];
        if (v > bv || (v == bv && i < bi)) { bv = v; bi = i; }
    }
    out[j]         = (float)bi;
    out[A_DIM + j] = bv * g_invSty[j];
}

// ---------------------------------------------------------------------------
extern "C" void kernel_launch(void* const* d_in, const int* in_sizes, int n_in,
                              void* d_out, int out_size) {
    const float* model = (const float*)d_in[0];
    const float* style = (const float*)d_in[1];
    float* out = (float*)d_out;

    cudaFuncSetAttribute(gemm_mma, cudaFuncAttributeMaxDynamicSharedMemorySize, SMEM_BYTES);

    unfold_part<<<dim3(512, 8), 192>>>(model, 0);
    unfold_part<<<dim3(512, 8), 192>>>(style, 1);
    norm_finish<<<36, 256>>>();
    gemm_mma<<<NPERS, 128, SMEM_BYTES>>>();
    final_kernel<<<A_DIM / 256, 256>>>(out);
}

// round 15
// speedup vs baseline: 1.0944x; 1.0944x over previous
#include <cuda_runtime.h>
#include <cuda_fp16.h>
#include <math.h>
#include <stdint.h>

#define A_DIM 4608
#define L_DIM 4096
#define H_DIM 192
#define W_DIM 192
#define NTILE 36
#define NTILES_TOTAL (NTILE * NTILE)
#define BK    32
#define NIT   (3 * (L_DIM / BK))   // 384
#define PITCH 80
#define STAGE (256 * PITCH)        // 20480 B
#define NSTG  4
#define SMEM_BYTES (NSTG * STAGE)  // 81920
#define NPERS 296

__device__ __half g_imgHi[(size_t)A_DIM * L_DIM];
__device__ __half g_imgLo[(size_t)A_DIM * L_DIM];
__device__ __half g_styHi[(size_t)A_DIM * L_DIM];
__device__ __half g_styLo[(size_t)A_DIM * L_DIM];
__device__ float g_invImg[A_DIM];
__device__ float g_invSty[A_DIM];
__device__ float g_np[2 * A_DIM * 8];
__device__ float g_pmax[NTILE * A_DIM];
__device__ int   g_pidx[NTILE * A_DIM];
__device__ unsigned int g_tileCtr;

__device__ __forceinline__ uint32_t smem_u32(const void* p) {
    uint32_t a;
    asm("{ .reg .u64 t; cvta.to.shared.u64 t, %1; cvt.u32.u64 %0, t; }" : "=r"(a) : "l"(p));
    return a;
}
#define CP16(dst, src) \
    asm volatile("cp.async.cg.shared.global [%0], [%1], 16;" :: "r"(dst), "l"(src) : "memory")
#define CP_COMMIT() asm volatile("cp.async.commit_group;" ::: "memory")
#define CP_WAIT2()  asm volatile("cp.async.wait_group 2;" ::: "memory")
#define CP_WAIT0()  asm volatile("cp.async.wait_group 0;" ::: "memory")
#define LDSM4(r0, r1, r2, r3, a) \
    asm volatile("ldmatrix.sync.aligned.m8n8.x4.shared.b16 {%0,%1,%2,%3}, [%4];" \
        : "=r"(r0), "=r"(r1), "=r"(r2), "=r"(r3) : "r"(a))
#define MMA_F16(c, a, b) \
    asm volatile("mma.sync.aligned.m16n8k16.row.col.f32.f16.f16.f32 " \
        "{%0,%1,%2,%3}, {%4,%5,%6,%7}, {%8,%9}, {%0,%1,%2,%3};" \
        : "+f"((c)[0]), "+f"((c)[1]), "+f"((c)[2]), "+f"((c)[3]) \
        : "r"((a)[0]), "r"((a)[1]), "r"((a)[2]), "r"((a)[3]), "r"((b)[0]), "r"((b)[1]))

// ---------------------------------------------------------------------------
// 1) unfold + fp16 hi/lo split + norm partials (block = (c, phc); 8 ph each)
// ---------------------------------------------------------------------------
__global__ void __launch_bounds__(192)
unfold_part(const float* __restrict__ in, int which) {
    __shared__ float sh[576];
    __shared__ float red[9][64];
    const int c = blockIdx.x, phc = blockIdx.y;
    const int tid = threadIdx.x;
    const float* src = in + (size_t)c * H_DIM * W_DIM;
    __half* outHi = which ? g_styHi : g_imgHi;
    __half* outLo = which ? g_styLo : g_imgLo;

    float acc0 = 0.0f, acc1 = 0.0f, acc2 = 0.0f;
    for (int pp = 0; pp < 8; ++pp) {
        const int ph = phc * 8 + pp;
        const float* rsrc = src + ph * 3 * W_DIM;
        sh[tid]       = rsrc[tid];
        sh[tid + 192] = rsrc[tid + 192];
        sh[tid + 384] = rsrc[tid + 384];
        __syncthreads();
        #pragma unroll
        for (int j = 0; j < 3; ++j) {
            int i = tid + j * 192;
            int seg = i >> 6, pw = i & 63;
            int kh = seg / 3, kw = seg - kh * 3;
            float v = sh[kh * W_DIM + pw * 3 + kw];
            __half hi = __float2half_rn(v);
            __half lo = __float2half_rn(v - __half2float(hi));
            size_t o = ((size_t)c * 9 + seg) * L_DIM + ph * 64 + pw;
            outHi[o] = hi;
            outLo[o] = lo;
            if (j == 0) acc0 = fmaf(v, v, acc0);
            else if (j == 1) acc1 = fmaf(v, v, acc1);
            else acc2 = fmaf(v, v, acc2);
        }
        __syncthreads();
    }
    red[(tid >> 6)][tid & 63]     = acc0;
    red[3 + (tid >> 6)][tid & 63] = acc1;
    red[6 + (tid >> 6)][tid & 63] = acc2;
    __syncthreads();
    if (tid < 9) {
        float s = 0.0f;
        #pragma unroll 8
        for (int k = 0; k < 64; ++k) s += red[tid][k];
        g_np[((size_t)which * A_DIM + c * 9 + tid) * 8 + phc] = s;
    }
}

// ---------------------------------------------------------------------------
// 2) norm finish + tile-counter reset
// ---------------------------------------------------------------------------
__global__ void norm_finish() {
    int i = blockIdx.x * blockDim.x + threadIdx.x;
    if (i == 0) g_tileCtr = 0;
    if (i >= 2 * A_DIM) return;
    float s = 0.0f;
    #pragma unroll
    for (int k = 0; k < 8; ++k) s += g_np[(size_t)i * 8 + k];
    float inv = 1.0f / sqrtf(s);
    if (i < A_DIM) g_invImg[i] = inv;
    else           g_invSty[i - A_DIM] = inv;
}

// ---------------------------------------------------------------------------
// 3) persistent fp16x3 GEMM, 128x128 tile, 4 warps (64x64 each), BK=32,
//    4-stage cp.async ring (wait_group 2 -> 2-3 iters of load lead time).
// ---------------------------------------------------------------------------
__global__ void __launch_bounds__(128, 2)
gemm_mma() {
    extern __shared__ char smem[];
    __shared__ int sh_tile;
    const uint32_t sb = smem_u32(smem);
    const int tid = threadIdx.x;
    const int wid = tid >> 5, lane = tid & 31;
    const int warp_m = wid & 1, warp_n = wid >> 1;
    const int m_base = warp_m * 64, n_base = warp_n * 64;

    const uint32_t aOff = (uint32_t)(m_base + (lane & 15)) * PITCH + (lane >> 4) * 16;
    const uint32_t bOff = 128u * PITCH
                        + (uint32_t)(n_base + ((lane >> 4) * 8) + (lane & 7)) * PITCH
                        + (((lane >> 3) & 1) * 16);

    for (;;) {
        if (tid == 0) sh_tile = (int)atomicAdd(&g_tileCtr, 1u);
        __syncthreads();
        const int tile = sh_tile;
        if (tile >= NTILES_TOTAL) break;
        const int bm = tile / NTILE, bn = tile - bm * NTILE;
        const int m0 = bm * 128, n0 = bn * 128;

        const __half* passA[3] = {
            g_styHi + (size_t)m0 * L_DIM, g_styHi + (size_t)m0 * L_DIM, g_styLo + (size_t)m0 * L_DIM };
        const __half* passB[3] = {
            g_imgHi + (size_t)n0 * L_DIM, g_imgLo + (size_t)n0 * L_DIM, g_imgHi + (size_t)n0 * L_DIM };

        auto issue = [&](int it, int s) {
            const int p = it / (L_DIM / BK);
            const int kx = (it % (L_DIM / BK)) * BK;
            const __half* gA = passA[p] + kx;
            const __half* gB = passB[p] + kx;
            const uint32_t st = sb + s * STAGE;
            #pragma unroll
            for (int u = 0; u < 8; ++u) {
                int idx = u * 128 + tid;
                int row = idx >> 2, col = idx & 3;
                const __half* g = (row < 128)
                    ? gA + (size_t)row * L_DIM + col * 8
                    : gB + (size_t)(row - 128) * L_DIM + col * 8;
                CP16(st + row * PITCH + col * 16, g);
            }
            CP_COMMIT();
        };

        float acc[4][8][4];
        #pragma unroll
        for (int i = 0; i < 4; ++i)
            #pragma unroll
            for (int j = 0; j < 8; ++j)
                #pragma unroll
                for (int k = 0; k < 4; ++k) acc[i][j][k] = 0.0f;

        issue(0, 0);
        issue(1, 1);
        issue(2, 2);

        for (int it = 0; it < NIT; ++it) {
            const int s = it % NSTG;
            if (it + 3 < NIT) { CP_WAIT2(); } else { CP_WAIT0(); }
            __syncthreads();
            if (it + 3 < NIT) issue(it + 3, (it + 3) % NSTG);

            const uint32_t st = sb + s * STAGE;
            #pragma unroll
            for (int ks = 0; ks < 2; ++ks) {
                uint32_t a0[4][4];
                #pragma unroll
                for (int mt = 0; mt < 4; ++mt)
                    LDSM4(a0[mt][0], a0[mt][1], a0[mt][2], a0[mt][3],
                          st + aOff + mt * 16 * PITCH + ks * 32);
                uint32_t b0[4][4];
                #pragma unroll
                for (int np = 0; np < 4; ++np)
                    LDSM4(b0[np][0], b0[np][1], b0[np][2], b0[np][3],
                          st + bOff + np * 16 * PITCH + ks * 32);
                #pragma unroll
                for (int mt = 0; mt < 4; ++mt)
                    #pragma unroll
                    for (int np = 0; np < 4; ++np) {
                        MMA_F16(acc[mt][np * 2],     a0[mt], (&b0[np][0]));
                        MMA_F16(acc[mt][np * 2 + 1], a0[mt], (&b0[np][2]));
                    }
            }
            __syncthreads();
        }

        // ---- register epilogue: column max of acc * g_invImg[row] ----
        float invR[8];
        #pragma unroll
        for (int mt = 0; mt < 4; ++mt)
            #pragma unroll
            for (int h = 0; h < 2; ++h)
                invR[mt * 2 + h] = g_invImg[m0 + m_base + mt * 16 + h * 8 + (lane >> 2)];

        float* pv = (float*)smem;
        int*   pi = (int*)(smem + 2 * 128 * 4);

        #pragma unroll
        for (int j = 0; j < 8; ++j)
            #pragma unroll
            for (int p = 0; p < 2; ++p) {
                float bv = -3.402823466e38f;
                int bi = 0x7fffffff;
                #pragma unroll
                for (int mt = 0; mt < 4; ++mt)
                    #pragma unroll
                    for (int h = 0; h < 2; ++h) {
                        float v = acc[mt][j][h * 2 + p] * invR[mt * 2 + h];
                        int row = m0 + m_base + mt * 16 + h * 8 + (lane >> 2);
                        if (v > bv || (v == bv && row < bi)) { bv = v; bi = row; }
                    }
                #pragma unroll
                for (int o = 4; o < 32; o <<= 1) {
                    float ov = __shfl_xor_sync(0xffffffffu, bv, o);
                    int   oi = __shfl_xor_sync(0xffffffffu, bi, o);
                    if (ov > bv || (ov == bv && oi < bi)) { bv = ov; bi = oi; }
                }
                if ((lane >> 2) == 0) {
                    int col = n_base + j * 8 + (lane & 3) * 2 + p;
                    pv[warp_m * 128 + col] = bv;
                    pi[warp_m * 128 + col] = bi;
                }
            }
        __syncthreads();

        if (tid < 128) {
            float bv = pv[tid];
            int bi = pi[tid];
            float v = pv[128 + tid];
            int  i2 = pi[128 + tid];
            if (v > bv || (v == bv && i2 < bi)) { bv = v; bi = i2; }
            g_pmax[bm * A_DIM + n0 + tid] = bv;
            g_pidx[bm * A_DIM + n0 + tid] = bi;
        }
        __syncthreads();
    }
}

// ---------------------------------------------------------------------------
// 4) final reduce
// ---------------------------------------------------------------------------
__global__ void final_kernel(float* __restrict__ out) {
    int j = blockIdx.x * blockDim.x + threadIdx.x;
    if (j >= A_DIM) return;
    float bv = g_pmax[j];
    int bi = g_pidx[j];
    #pragma unroll
    for (int t = 1; t < NTILE; ++t) {
        float v = g_pmax[t * A_DIM + j];
        int i = g_pidx[t * A_DIM + j];
        if (v > bv || (v == bv && i < bi)) { bv = v; bi = i; }
    }
    out[j]         = (float)bi;
    out[A_DIM + j] = bv * g_invSty[j];
}

// ---------------------------------------------------------------------------
extern "C" void kernel_launch(void* const* d_in, const int* in_sizes, int n_in,
                              void* d_out, int out_size) {
    const float* model = (const float*)d_in[0];
    const float* style = (const float*)d_in[1];
    float* out = (float*)d_out;

    cudaFuncSetAttribute(gemm_mma, cudaFuncAttributeMaxDynamicSharedMemorySize, SMEM_BYTES);

    unfold_part<<<dim3(512, 8), 192>>>(model, 0);
    unfold_part<<<dim3(512, 8), 192>>>(style, 1);
    norm_finish<<<36, 256>>>();
    gemm_mma<<<NPERS, 128, SMEM_BYTES>>>();
    final_kernel<<<A_DIM / 256, 256>>>(out);
}